// round 1
// baseline (speedup 1.0000x reference)
#include <cuda_runtime.h>
#include <math.h>

#define N_TOK 4096
#define EMB   1024

// Scratch (alloc-free rule: __device__ globals)
__device__ float g_Q[(size_t)N_TOK * EMB];
__device__ float g_K[(size_t)N_TOK * EMB];
__device__ float g_S[(size_t)N_TOK * N_TOK];

// ---------------------------------------------------------------------------
// Tiled fp32 SGEMM: C[M,N] = alpha * A[M,K] @ op(B)
//   TRANS_B=false: B is [K,N] row-major
//   TRANS_B=true : B is [N,K] row-major, use B^T
// BM=BN=128, BK=16, 256 threads, 8x8 per-thread tile.
// All dims here are multiples of the tile sizes (4096/1024), no bounds checks.
// ---------------------------------------------------------------------------
template <bool TRANS_B>
__global__ __launch_bounds__(256, 2)
void sgemm_kernel(const float* __restrict__ A, const float* __restrict__ B,
                  float* __restrict__ C, int M, int N, int K, float alpha)
{
    constexpr int BM = 128, BN = 128, BK = 16;
    __shared__ float As[BK][BM];
    __shared__ float Bs[BK][BN];

    const int t  = threadIdx.x;
    const int bm = blockIdx.y * BM;
    const int bn = blockIdx.x * BN;
    const int tx = t & 15;   // 0..15 -> n
    const int ty = t >> 4;   // 0..15 -> m

    float acc[8][8];
#pragma unroll
    for (int i = 0; i < 8; i++)
#pragma unroll
        for (int j = 0; j < 8; j++) acc[i][j] = 0.f;

    for (int k0 = 0; k0 < K; k0 += BK) {
        // ---- load A tile (BMxBK), store transposed As[k][m] ----
#pragma unroll
        for (int i = 0; i < 2; i++) {
            int id  = t + i * 256;      // 0..511 float4 slots
            int row = id >> 2;          // 0..127
            int c4  = (id & 3) << 2;    // 0,4,8,12
            float4 v = *(const float4*)&A[(size_t)(bm + row) * K + k0 + c4];
            As[c4 + 0][row] = v.x;
            As[c4 + 1][row] = v.y;
            As[c4 + 2][row] = v.z;
            As[c4 + 3][row] = v.w;
        }
        // ---- load B tile into Bs[k][n] ----
        if (TRANS_B) {
#pragma unroll
            for (int i = 0; i < 2; i++) {
                int id  = t + i * 256;
                int row = id >> 2;        // n 0..127
                int c4  = (id & 3) << 2;  // k
                float4 v = *(const float4*)&B[(size_t)(bn + row) * K + k0 + c4];
                Bs[c4 + 0][row] = v.x;
                Bs[c4 + 1][row] = v.y;
                Bs[c4 + 2][row] = v.z;
                Bs[c4 + 3][row] = v.w;
            }
        } else {
#pragma unroll
            for (int i = 0; i < 2; i++) {
                int id  = t + i * 256;
                int row = id >> 5;        // k 0..15
                int c4  = (id & 31) << 2; // n 0..124
                *(float4*)&Bs[row][c4] =
                    *(const float4*)&B[(size_t)(k0 + row) * N + bn + c4];
            }
        }
        __syncthreads();

        // ---- compute ----
#pragma unroll
        for (int kk = 0; kk < BK; kk++) {
            float a[8], b[8];
#pragma unroll
            for (int i = 0; i < 4; i++) {
                float4 va = *(const float4*)&As[kk][ty * 8 + i * 4 - (i>=2 ? 4 : 0) + (i>=2 ? 4:0)];
                (void)va; // (kept simple below)
            }
            // simple scalar shared reads (broadcast-friendly)
#pragma unroll
            for (int i = 0; i < 8; i++) a[i] = As[kk][ty * 8 + i];
#pragma unroll
            for (int j = 0; j < 8; j++) b[j] = Bs[kk][tx * 8 + j];
#pragma unroll
            for (int i = 0; i < 8; i++)
#pragma unroll
                for (int j = 0; j < 8; j++)
                    acc[i][j] = fmaf(a[i], b[j], acc[i][j]);
        }
        __syncthreads();
    }

    // ---- epilogue ----
#pragma unroll
    for (int i = 0; i < 8; i++) {
        size_t row = (size_t)(bm + ty * 8 + i);
#pragma unroll
        for (int j = 0; j < 8; j += 4) {
            float4 v;
            v.x = acc[i][j + 0] * alpha;
            v.y = acc[i][j + 1] * alpha;
            v.z = acc[i][j + 2] * alpha;
            v.w = acc[i][j + 3] * alpha;
            *(float4*)&C[row * N + bn + tx * 8 + j] = v;
        }
    }
}

// ---------------------------------------------------------------------------
// Row softmax in place: S[row, :] for row-length N (one block per row)
// ---------------------------------------------------------------------------
__global__ __launch_bounds__(256)
void softmax_rows_kernel(float* __restrict__ S, int N)
{
    const int row = blockIdx.x;
    float* p = S + (size_t)row * N;
    const int t = threadIdx.x;
    __shared__ float red[256];

    // max
    float m = -INFINITY;
    for (int i = t; i < N; i += 256) m = fmaxf(m, p[i]);
    red[t] = m;
    __syncthreads();
    for (int s = 128; s > 0; s >>= 1) {
        if (t < s) red[t] = fmaxf(red[t], red[t + s]);
        __syncthreads();
    }
    m = red[0];
    __syncthreads();

    // exp + sum
    float sum = 0.f;
    for (int i = t; i < N; i += 256) {
        float e = __expf(p[i] - m);
        p[i] = e;
        sum += e;
    }
    red[t] = sum;
    __syncthreads();
    for (int s = 128; s > 0; s >>= 1) {
        if (t < s) red[t] += red[t + s];
        __syncthreads();
    }
    const float inv = 1.0f / red[0];
    __syncthreads();

    for (int i = t; i < N; i += 256) p[i] *= inv;
}

// ---------------------------------------------------------------------------
extern "C" void kernel_launch(void* const* d_in, const int* in_sizes, int n_in,
                              void* d_out, int out_size)
{
    const float* X  = (const float*)d_in[0];  // [4096,1024]
    const float* Wq = (const float*)d_in[1];  // [1024,1024]
    const float* Wk = (const float*)d_in[2];  // [1024,1024]
    float* out      = (float*)d_out;          // [4096,1024]

    float *pQ, *pK, *pS;
    cudaGetSymbolAddress((void**)&pQ, g_Q);
    cudaGetSymbolAddress((void**)&pK, g_K);
    cudaGetSymbolAddress((void**)&pS, g_S);

    const float scale = 1.0f / 32.0f;  // 1/sqrt(1024)

    // Q = X @ Wq ; K = X @ Wk   (M=4096, N=1024, K=1024)
    {
        dim3 grid(EMB / 128, N_TOK / 128);
        sgemm_kernel<false><<<grid, 256>>>(X, Wq, pQ, N_TOK, EMB, EMB, 1.0f);
        sgemm_kernel<false><<<grid, 256>>>(X, Wk, pK, N_TOK, EMB, EMB, 1.0f);
    }

    // S = (Q @ K^T) * scale   (M=N=4096, K=1024)
    {
        dim3 grid(N_TOK / 128, N_TOK / 128);
        sgemm_kernel<true><<<grid, 256>>>(pQ, pK, pS, N_TOK, N_TOK, EMB, scale);
    }

    // softmax rows
    softmax_rows_kernel<<<N_TOK, 256>>>(pS, N_TOK);

    // out = S @ X   (M=4096, N=1024, K=4096)
    {
        dim3 grid(EMB / 128, N_TOK / 128);
        sgemm_kernel<false><<<grid, 256>>>(pS, X, out, N_TOK, EMB, N_TOK, 1.0f);
    }
}

// round 3
// speedup vs baseline: 2.0131x; 2.0131x over previous
#include <cuda_runtime.h>
#include <cuda_bf16.h>
#include <math.h>
#include <stdint.h>

#define N_TOK 4096
#define EMB   1024

typedef __nv_bfloat16 bf16;

// ---------------------------------------------------------------------------
// Device scratch (alloc-free rule: __device__ globals)
// ---------------------------------------------------------------------------
__device__ __align__(256) bf16 gXs0[(size_t)N_TOK * EMB];
__device__ __align__(256) bf16 gXs1[(size_t)N_TOK * EMB];
__device__ __align__(256) bf16 gXs2[(size_t)N_TOK * EMB];
__device__ __align__(256) bf16 gXT0[(size_t)EMB * N_TOK];
__device__ __align__(256) bf16 gXT1[(size_t)EMB * N_TOK];
__device__ __align__(256) bf16 gWq0[(size_t)EMB * EMB];
__device__ __align__(256) bf16 gWq1[(size_t)EMB * EMB];
__device__ __align__(256) bf16 gWq2[(size_t)EMB * EMB];
__device__ __align__(256) bf16 gWk0[(size_t)EMB * EMB];
__device__ __align__(256) bf16 gWk1[(size_t)EMB * EMB];
__device__ __align__(256) bf16 gWk2[(size_t)EMB * EMB];
__device__ __align__(256) bf16 gQ0[(size_t)N_TOK * EMB];
__device__ __align__(256) bf16 gQ1[(size_t)N_TOK * EMB];
__device__ __align__(256) bf16 gQ2[(size_t)N_TOK * EMB];
__device__ __align__(256) bf16 gK0[(size_t)N_TOK * EMB];
__device__ __align__(256) bf16 gK1[(size_t)N_TOK * EMB];
__device__ __align__(256) bf16 gK2[(size_t)N_TOK * EMB];
__device__ __align__(256) float gS[(size_t)N_TOK * N_TOK];
__device__ __align__(256) bf16 gSh[(size_t)N_TOK * N_TOK];
__device__ __align__(256) bf16 gSl[(size_t)N_TOK * N_TOK];

// ---------------------------------------------------------------------------
// helpers
// ---------------------------------------------------------------------------
__device__ __forceinline__ uint32_t smem_u32(const void* p) {
    return (uint32_t)__cvta_generic_to_shared(p);
}
__device__ __forceinline__ void cp16(uint32_t dst, const void* src) {
    asm volatile("cp.async.cg.shared.global [%0], [%1], 16;" :: "r"(dst), "l"(src));
}
__device__ __forceinline__ void cp_commit() { asm volatile("cp.async.commit_group;" ::: "memory"); }
__device__ __forceinline__ void cp_wait1()  { asm volatile("cp.async.wait_group 1;" ::: "memory"); }

__device__ __forceinline__ void ldsm_x4(uint32_t* r, uint32_t addr) {
    asm volatile("ldmatrix.sync.aligned.m8n8.x4.shared.b16 {%0,%1,%2,%3}, [%4];"
                 : "=r"(r[0]), "=r"(r[1]), "=r"(r[2]), "=r"(r[3]) : "r"(addr));
}

__device__ __forceinline__ void mma16816(float* d, const uint32_t* a, const uint32_t* b) {
    asm volatile(
        "mma.sync.aligned.m16n8k16.row.col.f32.bf16.bf16.f32 "
        "{%0,%1,%2,%3}, {%4,%5,%6,%7}, {%8,%9}, {%0,%1,%2,%3};"
        : "+f"(d[0]), "+f"(d[1]), "+f"(d[2]), "+f"(d[3])
        : "r"(a[0]), "r"(a[1]), "r"(a[2]), "r"(a[3]), "r"(b[0]), "r"(b[1]));
}

__device__ __forceinline__ void split3(float v, bf16& h, bf16& m, bf16& l) {
    h = __float2bfloat16_rn(v);
    float r1 = v - __bfloat162float(h);
    m = __float2bfloat16_rn(r1);
    float r2 = r1 - __bfloat162float(m);
    l = __float2bfloat16_rn(r2);
}

// swizzled addr inside a 128row x 128B tile: row r, 16B-chunk c
__device__ __forceinline__ uint32_t sw_addr(uint32_t base, int r, int c) {
    return base + r * 128 + (((uint32_t)(c ^ (r & 7))) << 4);
}

// ---------------------------------------------------------------------------
// Tile loader: NSP splits, 128 rows x 64 bf16 (128B rows, swizzled), 16KB each
// ---------------------------------------------------------------------------
template <int NSP>
__device__ __forceinline__ void load_tiles(const bf16* p0, const bf16* p1, const bf16* p2,
                                           uint32_t base, int row0, int K, int k0, int tid)
{
    const bf16* ps[3] = { p0, p1, p2 };
#pragma unroll
    for (int s = 0; s < NSP; s++) {
#pragma unroll
        for (int i = 0; i < 4; i++) {
            int idx = i * 256 + tid;
            int r = idx >> 3;
            int c = idx & 7;
            const bf16* src = ps[s] + (size_t)(row0 + r) * K + k0 + c * 8;
            cp16(sw_addr(base + s * 16384, r, c), src);
        }
    }
}

// ---------------------------------------------------------------------------
// HMMA split-GEMM. C[m,n] = alpha * sum_p A_{PA[p]}[m,:] . B_{PB[p]}[n,:]
// A splits row-major [M,K]; B splits row-major [N,K]. CTA tile 128x128, KC=64.
// 8 warps: warp_m = wid&1 (64 rows), warp_n = wid>>1 (32 cols).
// EPI 0: fp32 store to Cf.  EPI 1: 3-way bf16 split store to C0/C1/C2.
// ---------------------------------------------------------------------------
template <int NSPA, int NSPB, int NPROD, int EPI>
__global__ __launch_bounds__(256, 1)
void hmma_gemm_kernel(const bf16* __restrict__ A0, const bf16* __restrict__ A1, const bf16* __restrict__ A2,
                      const bf16* __restrict__ B0, const bf16* __restrict__ B1, const bf16* __restrict__ B2,
                      float* __restrict__ Cf,
                      bf16* __restrict__ C0, bf16* __restrict__ C1, bf16* __restrict__ C2,
                      int K, int KITERS, int ldc, float alpha)
{
    extern __shared__ char smem[];
    const uint32_t ABASE = smem_u32(smem);
    const uint32_t BBASE = ABASE + 2 * NSPA * 16384;

    const int tid = threadIdx.x;
    const int wid = tid >> 5;
    const int lid = tid & 31;
    const int m0 = blockIdx.y * 128;
    const int n0 = blockIdx.x * 128;
    const int m0w = (wid & 1) * 64;
    const int n0w = (wid >> 1) * 32;

    float acc[4][4][4];
#pragma unroll
    for (int i = 0; i < 4; i++)
#pragma unroll
        for (int j = 0; j < 4; j++)
#pragma unroll
            for (int k = 0; k < 4; k++) acc[i][j][k] = 0.f;

    // ldmatrix lane roles
    const int sel = lid >> 3;
    const int lrow = lid & 7;
    // A x4: M0=(rb0,kb0) M1=(rb1,kb0) M2=(rb0,kb1) M3=(rb1,kb1)
    const int a_rb = (sel & 1) * 8;
    const int a_kb = sel >> 1;
    // B x4: M0=(nb0,kb0) M1=(nb0,kb1) M2=(nb1,kb0) M3=(nb1,kb1)
    const int b_nb = (sel >> 1) * 8;
    const int b_kb = sel & 1;

    // prologue
    load_tiles<NSPA>(A0, A1, A2, ABASE, m0, K, 0, tid);
    load_tiles<NSPB>(B0, B1, B2, BBASE, n0, K, 0, tid);
    cp_commit();
    if (KITERS > 1) {
        load_tiles<NSPA>(A0, A1, A2, ABASE + NSPA * 16384, m0, K, 64, tid);
        load_tiles<NSPB>(B0, B1, B2, BBASE + NSPB * 16384, n0, K, 64, tid);
    }
    cp_commit();

    constexpr int PA[6] = { 0, 0, 1, 1, 0, 2 };
    constexpr int PB[6] = { 0, 1, 0, 1, 2, 0 };

    for (int it = 0; it < KITERS; it++) {
        const int stage = it & 1;
        cp_wait1();
        __syncthreads();

        const uint32_t abase_st = ABASE + stage * NSPA * 16384;
        const uint32_t bbase_st = BBASE + stage * NSPB * 16384;

#pragma unroll
        for (int p = 0; p < NPROD; p++) {
            const uint32_t ab = abase_st + PA[p] * 16384;
            const uint32_t bb = bbase_st + PB[p] * 16384;
#pragma unroll
            for (int ks = 0; ks < 4; ks++) {
                uint32_t afr[4][4];
#pragma unroll
                for (int mt = 0; mt < 4; mt++)
                    ldsm_x4(afr[mt], sw_addr(ab, m0w + mt * 16 + a_rb + lrow, ks * 2 + a_kb));
                uint32_t bfr[2][4];
#pragma unroll
                for (int j = 0; j < 2; j++)
                    ldsm_x4(bfr[j], sw_addr(bb, n0w + j * 16 + b_nb + lrow, ks * 2 + b_kb));
#pragma unroll
                for (int mt = 0; mt < 4; mt++)
#pragma unroll
                    for (int nt = 0; nt < 4; nt++)
                        mma16816(acc[mt][nt], afr[mt], &bfr[nt >> 1][(nt & 1) * 2]);
            }
        }
        __syncthreads();

        if (it + 2 < KITERS) {
            load_tiles<NSPA>(A0, A1, A2, abase_st, m0, K, (it + 2) * 64, tid);
            load_tiles<NSPB>(B0, B1, B2, bbase_st, n0, K, (it + 2) * 64, tid);
        }
        cp_commit();
    }

    // epilogue: lane l owns rows gr, gr+8 and col pair (l&3)*2 of each 16x8 frag
    const int gr = lid >> 2;
    const int cp = (lid & 3) * 2;
#pragma unroll
    for (int mt = 0; mt < 4; mt++) {
#pragma unroll
        for (int half = 0; half < 2; half++) {
            const int row = m0 + m0w + mt * 16 + gr + half * 8;
#pragma unroll
            for (int nt = 0; nt < 4; nt++) {
                const int col = n0 + n0w + nt * 8 + cp;
                float v0 = acc[mt][nt][half * 2 + 0] * alpha;
                float v1 = acc[mt][nt][half * 2 + 1] * alpha;
                if (EPI == 0) {
                    *(float2*)&Cf[(size_t)row * ldc + col] = make_float2(v0, v1);
                } else {
                    bf16 h0, mm0, l0, h1, mm1, l1;
                    split3(v0, h0, mm0, l0);
                    split3(v1, h1, mm1, l1);
                    size_t off = (size_t)row * ldc + col;
                    *(__nv_bfloat162*)&C0[off] = __nv_bfloat162(h0, h1);
                    *(__nv_bfloat162*)&C1[off] = __nv_bfloat162(mm0, mm1);
                    *(__nv_bfloat162*)&C2[off] = __nv_bfloat162(l0, l1);
                }
            }
        }
    }
}

// ---------------------------------------------------------------------------
// Elementwise 3-way split
// ---------------------------------------------------------------------------
__global__ __launch_bounds__(256)
void split3_kernel(const float* __restrict__ in, bf16* __restrict__ o0,
                   bf16* __restrict__ o1, bf16* __restrict__ o2, int n)
{
    for (int i = blockIdx.x * 256 + threadIdx.x; i < n; i += gridDim.x * 256) {
        bf16 h, m, l;
        split3(in[i], h, m, l);
        o0[i] = h; o1[i] = m; o2[i] = l;
    }
}

// ---------------------------------------------------------------------------
// Transposing split: in [R,C] fp32 -> out[c][r] splits (NS outputs)
// ---------------------------------------------------------------------------
template <int NS>
__global__ __launch_bounds__(256)
void tsplit_kernel(const float* __restrict__ in, bf16* __restrict__ o0,
                   bf16* __restrict__ o1, bf16* __restrict__ o2, int R, int C)
{
    __shared__ float t[32][33];
    const int cb = blockIdx.x * 32, rb = blockIdx.y * 32;
    const int tx = threadIdx.x & 31, ty = threadIdx.x >> 5;
#pragma unroll
    for (int i = 0; i < 32; i += 8)
        t[ty + i][tx] = in[(size_t)(rb + ty + i) * C + cb + tx];
    __syncthreads();
#pragma unroll
    for (int i = 0; i < 32; i += 8) {
        float v = t[tx][ty + i];
        bf16 h, m, l;
        split3(v, h, m, l);
        size_t off = (size_t)(cb + ty + i) * R + rb + tx;
        o0[off] = h;
        o1[off] = m;
        if (NS == 3) o2[off] = l;
    }
}

// ---------------------------------------------------------------------------
// Row softmax of logits -> 2-term bf16 split
// ---------------------------------------------------------------------------
__global__ __launch_bounds__(256)
void softmax_split_kernel(const float* __restrict__ S, bf16* __restrict__ H, bf16* __restrict__ L)
{
    __shared__ float buf[N_TOK];
    __shared__ float red[256];
    const int row = blockIdx.x;
    const int t = threadIdx.x;
    const float* p = S + (size_t)row * N_TOK;

    float m = -INFINITY;
    for (int i = t; i < N_TOK; i += 256) {
        float v = p[i];
        buf[i] = v;
        m = fmaxf(m, v);
    }
    red[t] = m;
    __syncthreads();
    for (int s = 128; s > 0; s >>= 1) {
        if (t < s) red[t] = fmaxf(red[t], red[t + s]);
        __syncthreads();
    }
    m = red[0];
    __syncthreads();

    float sum = 0.f;
    for (int i = t; i < N_TOK; i += 256) {
        float e = __expf(buf[i] - m);
        buf[i] = e;
        sum += e;
    }
    red[t] = sum;
    __syncthreads();
    for (int s = 128; s > 0; s >>= 1) {
        if (t < s) red[t] += red[t + s];
        __syncthreads();
    }
    const float inv = 1.0f / red[0];
    __syncthreads();

    for (int i = t; i < N_TOK; i += 256) {
        float v = buf[i] * inv;
        bf16 h = __float2bfloat16_rn(v);
        float r1 = v - __bfloat162float(h);
        bf16 l = __float2bfloat16_rn(r1);
        size_t off = (size_t)row * N_TOK + i;
        H[off] = h;
        L[off] = l;
    }
}

// ---------------------------------------------------------------------------
extern "C" void kernel_launch(void* const* d_in, const int* in_sizes, int n_in,
                              void* d_out, int out_size)
{
    const float* X  = (const float*)d_in[0];
    const float* Wq = (const float*)d_in[1];
    const float* Wk = (const float*)d_in[2];
    float* out      = (float*)d_out;

    bf16 *xs0, *xs1, *xs2, *xt0, *xt1;
    bf16 *wq0, *wq1, *wq2, *wk0, *wk1, *wk2;
    bf16 *q0, *q1, *q2, *k0, *k1, *k2, *sh, *sl;
    float* s;
    cudaGetSymbolAddress((void**)&xs0, gXs0); cudaGetSymbolAddress((void**)&xs1, gXs1);
    cudaGetSymbolAddress((void**)&xs2, gXs2);
    cudaGetSymbolAddress((void**)&xt0, gXT0); cudaGetSymbolAddress((void**)&xt1, gXT1);
    cudaGetSymbolAddress((void**)&wq0, gWq0); cudaGetSymbolAddress((void**)&wq1, gWq1);
    cudaGetSymbolAddress((void**)&wq2, gWq2);
    cudaGetSymbolAddress((void**)&wk0, gWk0); cudaGetSymbolAddress((void**)&wk1, gWk1);
    cudaGetSymbolAddress((void**)&wk2, gWk2);
    cudaGetSymbolAddress((void**)&q0, gQ0); cudaGetSymbolAddress((void**)&q1, gQ1);
    cudaGetSymbolAddress((void**)&q2, gQ2);
    cudaGetSymbolAddress((void**)&k0, gK0); cudaGetSymbolAddress((void**)&k1, gK1);
    cudaGetSymbolAddress((void**)&k2, gK2);
    cudaGetSymbolAddress((void**)&s, gS);
    cudaGetSymbolAddress((void**)&sh, gSh); cudaGetSymbolAddress((void**)&sl, gSl);

    const int SM6 = 12 * 16384;  // 3+3 splits, 2 stages = 192KB
    const int SM3 = 8 * 16384;   // 2+2 splits, 2 stages = 128KB
    cudaFuncSetAttribute(hmma_gemm_kernel<3,3,6,1>, cudaFuncAttributeMaxDynamicSharedMemorySize, SM6);
    cudaFuncSetAttribute(hmma_gemm_kernel<3,3,6,0>, cudaFuncAttributeMaxDynamicSharedMemorySize, SM6);
    cudaFuncSetAttribute(hmma_gemm_kernel<2,2,3,0>, cudaFuncAttributeMaxDynamicSharedMemorySize, SM3);

    // 1) splits / transposes of inputs
    split3_kernel<<<2048, 256>>>(X, xs0, xs1, xs2, N_TOK * EMB);
    tsplit_kernel<3><<<dim3(EMB / 32, EMB / 32), 256>>>(Wq, wq0, wq1, wq2, EMB, EMB);
    tsplit_kernel<3><<<dim3(EMB / 32, EMB / 32), 256>>>(Wk, wk0, wk1, wk2, EMB, EMB);
    tsplit_kernel<2><<<dim3(EMB / 32, N_TOK / 32), 256>>>(X, xt0, xt1, nullptr, N_TOK, EMB);

    // 2) Q = X @ Wq, K = X @ Wk  (3-way split outputs)
    {
        dim3 grid(EMB / 128, N_TOK / 128);
        hmma_gemm_kernel<3,3,6,1><<<grid, 256, SM6>>>(xs0, xs1, xs2, wq0, wq1, wq2,
                                                      nullptr, q0, q1, q2, EMB, EMB / 64, EMB, 1.0f);
        hmma_gemm_kernel<3,3,6,1><<<grid, 256, SM6>>>(xs0, xs1, xs2, wk0, wk1, wk2,
                                                      nullptr, k0, k1, k2, EMB, EMB / 64, EMB, 1.0f);
    }

    // 3) S = (Q @ K^T) * 1/32  (fp32 logits)
    {
        dim3 grid(N_TOK / 128, N_TOK / 128);
        hmma_gemm_kernel<3,3,6,0><<<grid, 256, SM6>>>(q0, q1, q2, k0, k1, k2,
                                                      s, nullptr, nullptr, nullptr,
                                                      EMB, EMB / 64, N_TOK, 1.0f / 32.0f);
    }

    // 4) softmax rows -> 2-term split
    softmax_split_kernel<<<N_TOK, 256>>>(s, sh, sl);

    // 5) out = S @ X
    {
        dim3 grid(EMB / 128, N_TOK / 128);
        hmma_gemm_kernel<2,2,3,0><<<grid, 256, SM3>>>(sh, sl, nullptr, xt0, xt1, nullptr,
                                                      out, nullptr, nullptr, nullptr,
                                                      N_TOK, N_TOK / 64, EMB, 1.0f);
    }
}